// round 6
// baseline (speedup 1.0000x reference)
#include <cuda_runtime.h>
#include <cuda_fp16.h>
#include <cstdint>

// LSTM discriminator: B=2048, T=512, H=128.
// 128 CTAs x 512 threads; warp w owns j in [8w, 8w+8) of each gate.
// Gate-outer MMA ordering (i,g,f,o) with per-gate epilogue interleaved into
// the second k-half of the MMA stream, so MUFU hides under tensor.
// Sigmoid's 0.5 pre-scale folded into W_hh/bias for gates i,f,o.

#define T_STEPS 512
#define HDIM    128
#define MB      16
#define HSTR    136   // padded stride in halves (272B): LDSM + STS conflict-free

__device__ __forceinline__ __half2 tanh2(__half2 x) {
    uint32_t xi = *reinterpret_cast<uint32_t*>(&x), yi;
    asm("tanh.approx.f16x2 %0, %1;" : "=r"(yi) : "r"(xi));
    return *reinterpret_cast<__half2*>(&yi);
}

__device__ __forceinline__ void mma16816_f16(uint32_t d[2], const uint32_t a[4],
                                             const uint32_t b[2]) {
    asm volatile(
        "mma.sync.aligned.m16n8k16.row.col.f16.f16.f16.f16 "
        "{%0,%1}, {%2,%3,%4,%5}, {%6,%7}, {%0,%1};\n"
        : "+r"(d[0]), "+r"(d[1])
        : "r"(a[0]), "r"(a[1]), "r"(a[2]), "r"(a[3]), "r"(b[0]), "r"(b[1]));
}

__device__ __forceinline__ void ldsm_x4(uint32_t a[4], uint32_t saddr) {
    asm volatile(
        "ldmatrix.sync.aligned.m8n8.x4.shared.b16 {%0,%1,%2,%3}, [%4];"
        : "=r"(a[0]), "=r"(a[1]), "=r"(a[2]), "=r"(a[3])
        : "r"(saddr));
}

__global__ __launch_bounds__(512, 1)
void lstm_disc_kernel(
    const float* __restrict__ x,      // [B, T]
    const float* __restrict__ hx0,    // [B, H]
    const float* __restrict__ cx0,    // [B, H]
    const float* __restrict__ W_ih,   // [4H, 1]
    const float* __restrict__ W_hh,   // [4H, H]
    const float* __restrict__ b_ih,   // [4H]
    const float* __restrict__ b_hh,   // [4H]
    const float* __restrict__ W_mlp,  // [1, H]
    const float* __restrict__ b_mlp,  // [1]
    float* __restrict__ out)          // [B, 1]
{
    __shared__ float xs[MB][T_STEPS + 1];
    __shared__ __align__(16) __half hbuf[2][MB][HSTR];
    __shared__ __half2 wih2[4][64];   // W_ih pairs per gate (pre-halved for i,f,o)
    __shared__ __half2 bb2[4][64];    // (b_ih+b_hh) pairs per gate (pre-halved for i,f,o)

    const int tid  = threadIdx.x;
    const int w    = tid >> 5;   // warp 0..15
    const int l    = tid & 31;
    const int qr   = l >> 2;     // 0..7
    const int ql   = l & 3;      // 0..3
    const int brow = blockIdx.x * MB;

    // ---- one-time loads ----
    for (int i = tid; i < MB * T_STEPS; i += 512)
        xs[i / T_STEPS][i % T_STEPS] = x[(size_t)(brow + i / T_STEPS) * T_STEPS + (i % T_STEPS)];
    for (int i = tid; i < 4 * 64; i += 512) {
        int g = i >> 6, p = i & 63, j = 2 * p;
        float sc = (g == 2) ? 1.0f : 0.5f;   // halve for sigmoid gates i,f,o
        wih2[g][p] = __floats2half2_rn(sc * W_ih[g * HDIM + j], sc * W_ih[g * HDIM + j + 1]);
        bb2[g][p]  = __floats2half2_rn(sc * (b_ih[g * HDIM + j] + b_hh[g * HDIM + j]),
                                       sc * (b_ih[g * HDIM + j + 1] + b_hh[g * HDIM + j + 1]));
    }
    for (int i = tid; i < MB * HDIM; i += 512) {
        int r = i / HDIM, j = i % HDIM;
        hbuf[0][r][j] = __float2half(hx0[(size_t)(brow + r) * HDIM + j]);
    }

    // W_hh -> f16 B fragments in registers (pre-halved for gates i,f,o).
    uint32_t Bf[4][8][2];
    #pragma unroll
    for (int g = 0; g < 4; ++g) {
        float sc = (g == 2) ? 1.0f : 0.5f;
        #pragma unroll
        for (int kk = 0; kk < 8; ++kk) {
            int n = g * HDIM + w * 8 + qr;
            int k = kk * 16 + 2 * ql;
            float2 v0 = *reinterpret_cast<const float2*>(&W_hh[(size_t)n * HDIM + k]);
            float2 v1 = *reinterpret_cast<const float2*>(&W_hh[(size_t)n * HDIM + k + 8]);
            __half2 h0 = __floats2half2_rn(sc * v0.x, sc * v0.y);
            __half2 h1 = __floats2half2_rn(sc * v1.x, sc * v1.y);
            Bf[g][kk][0] = *reinterpret_cast<uint32_t*>(&h0);
            Bf[g][kk][1] = *reinterpret_cast<uint32_t*>(&h1);
        }
    }

    const int jp = w * 4 + ql;
    __half2 wi2[4], bi2[4];
    __syncthreads();
    #pragma unroll
    for (int g = 0; g < 4; ++g) { wi2[g] = wih2[g][jp]; bi2[g] = bb2[g][jp]; }

    __half2 cst[2];
    #pragma unroll
    for (int rr = 0; rr < 2; ++rr) {
        int r = brow + qr + 8 * rr;
        int j = w * 8 + 2 * ql;
        cst[rr] = __floats2half2_rn(cx0[(size_t)r * HDIM + j],
                                    cx0[(size_t)r * HDIM + j + 1]);
    }

    const int lrow = l & 15;
    const int lkof = (l >> 4) * 8;
    const __half2 h05 = __float2half2_rn(0.5f);

    // ---- recurrence ----
    #pragma unroll 1
    for (int t = 0; t < T_STEPS; ++t) {
        const int rb = t & 1, wbuf = rb ^ 1;

        // bias + x contribution (independent of MMA, issue early)
        __half2 pre[4][2];
        {
            __half2 x0 = __float2half2_rn(xs[qr][t]);
            __half2 x1 = __float2half2_rn(xs[qr + 8][t]);
            #pragma unroll
            for (int g = 0; g < 4; ++g) {
                pre[g][0] = __hfma2(x0, wi2[g], bi2[g]);
                pre[g][1] = __hfma2(x1, wi2[g], bi2[g]);
            }
        }

        uint32_t acc[4][2];
        #pragma unroll
        for (int g = 0; g < 4; ++g) { acc[g][0] = 0u; acc[g][1] = 0u; }

        uint32_t A[4][4];

        // ---- first k-half: kk 0..3, all gates ----
        #pragma unroll
        for (int kk = 0; kk < 4; ++kk)
            ldsm_x4(A[kk], (uint32_t)__cvta_generic_to_shared(
                &hbuf[rb][lrow][kk * 16 + lkof]));
        #pragma unroll
        for (int g = 0; g < 4; ++g)
            #pragma unroll
            for (int kk = 0; kk < 4; ++kk)
                mma16816_f16(acc[g], A[kk], Bf[g][kk]);

        // ---- second k-half: kk 4..7, gate order i(0), g(2), f(1), o(3),
        //      with per-gate epilogue interleaved ----
        #pragma unroll
        for (int kk = 0; kk < 4; ++kk)
            ldsm_x4(A[kk], (uint32_t)__cvta_generic_to_shared(
                &hbuf[rb][lrow][(kk + 4) * 16 + lkof]));

        // gate i
        #pragma unroll
        for (int kk = 0; kk < 4; ++kk)
            mma16816_f16(acc[0], A[kk], Bf[0][kk + 4]);
        __half2 ti[2];
        #pragma unroll
        for (int rr = 0; rr < 2; ++rr)
            ti[rr] = tanh2(__hadd2(*reinterpret_cast<__half2*>(&acc[0][rr]), pre[0][rr]));

        // gate g
        #pragma unroll
        for (int kk = 0; kk < 4; ++kk)
            mma16816_f16(acc[2], A[kk], Bf[2][kk + 4]);
        __half2 ig[2];
        #pragma unroll
        for (int rr = 0; rr < 2; ++rr) {
            __half2 gv = tanh2(__hadd2(*reinterpret_cast<__half2*>(&acc[2][rr]), pre[2][rr]));
            __half2 iv = __hfma2(ti[rr], h05, h05);
            ig[rr] = __hmul2(iv, gv);
        }

        // gate f
        #pragma unroll
        for (int kk = 0; kk < 4; ++kk)
            mma16816_f16(acc[1], A[kk], Bf[1][kk + 4]);
        __half2 tc[2];
        #pragma unroll
        for (int rr = 0; rr < 2; ++rr) {
            __half2 tf = tanh2(__hadd2(*reinterpret_cast<__half2*>(&acc[1][rr]), pre[1][rr]));
            __half2 fv = __hfma2(tf, h05, h05);
            __half2 c  = __hfma2(fv, cst[rr], ig[rr]);
            cst[rr] = c;
            tc[rr] = tanh2(c);
        }

        // gate o
        #pragma unroll
        for (int kk = 0; kk < 4; ++kk)
            mma16816_f16(acc[3], A[kk], Bf[3][kk + 4]);
        #pragma unroll
        for (int rr = 0; rr < 2; ++rr) {
            __half2 to = tanh2(__hadd2(*reinterpret_cast<__half2*>(&acc[3][rr]), pre[3][rr]));
            __half2 ov = __hfma2(to, h05, h05);
            __half2 hv = __hmul2(ov, tc[rr]);
            *reinterpret_cast<uint32_t*>(
                &hbuf[wbuf][qr + 8 * rr][w * 8 + 2 * ql]) =
                *reinterpret_cast<uint32_t*>(&hv);
        }
        __syncthreads();
    }

    // ---- final MLP + sigmoid ----  (h(T) in hbuf[0], T even)
    if (tid < 128) {
        int r = tid >> 3, q = tid & 7;
        float s = 0.f;
        #pragma unroll
        for (int k = 0; k < 16; ++k) {
            int j = q * 16 + k;
            s = fmaf(__half2float(hbuf[0][r][j]), W_mlp[j], s);
        }
        s += __shfl_xor_sync(0xffffffffu, s, 1);
        s += __shfl_xor_sync(0xffffffffu, s, 2);
        s += __shfl_xor_sync(0xffffffffu, s, 4);
        if (q == 0) {
            float z = s + b_mlp[0];
            out[brow + r] = 1.f / (1.f + __expf(-z));
        }
    }
}

extern "C" void kernel_launch(void* const* d_in, const int* in_sizes, int n_in,
                              void* d_out, int out_size) {
    const float* x     = (const float*)d_in[0];
    const float* hx0   = (const float*)d_in[1];
    const float* cx0   = (const float*)d_in[2];
    const float* W_ih  = (const float*)d_in[3];
    const float* W_hh  = (const float*)d_in[4];
    const float* b_ih  = (const float*)d_in[5];
    const float* b_hh  = (const float*)d_in[6];
    const float* W_mlp = (const float*)d_in[7];
    const float* b_mlp = (const float*)d_in[8];
    float* out = (float*)d_out;

    const int B = out_size;          // 2048
    dim3 grid(B / MB), block(512);
    lstm_disc_kernel<<<grid, block>>>(x, hx0, cx0, W_ih, W_hh, b_ih, b_hh,
                                      W_mlp, b_mlp, out);
}